// round 10
// baseline (speedup 1.0000x reference)
#include <cuda_runtime.h>
#include <math.h>

#define D_   64
#define T_   128
#define B_   64
#define R_   20
#define SEE_ 10
#define H_   4
#define C_   4
#define NT   512

// ---------------- transposed weight scratch (output-major rows) ----------------
__device__ __align__(16) float g_WbgT   [H_*D_*3*D_];   // [h][d][k]
__device__ __align__(16) float g_WbatchT[H_*D_*3*D_];   // [h][d][k]
__device__ __align__(16) float g_WbgintT[6*D_*6*D_];    // [j][k]
__device__ __align__(16) float g_WhisintT[6*D_*2*D_];   // [j][k]
__device__ __align__(16) float g_WinmapT[4*D_*10*D_];   // [j][k]
__device__ __align__(16) float g_WihT   [3*D_*4*D_];    // [j][k]
__device__ __align__(16) float g_WhhT   [3*D_*D_];      // [j][k]

__global__ void prep_kernel(const float* __restrict__ Wbg, const float* __restrict__ Wbatch,
                            const float* __restrict__ Wbgint, const float* __restrict__ Whisint,
                            const float* __restrict__ Winmap, const float* __restrict__ Wih,
                            const float* __restrict__ Whh)
{
  const int stride = gridDim.x*blockDim.x;
  const int i0 = blockIdx.x*blockDim.x + threadIdx.x;
  for (int o=i0; o<H_*D_*3*D_; o+=stride){
    int h=o/(D_*3*D_); int r=o-h*D_*3*D_; int d=r/(3*D_); int k=r-d*3*D_;
    int in=(h*3*D_+k)*D_+d;
    g_WbgT[o]=Wbg[in]; g_WbatchT[o]=Wbatch[in];
  }
  for (int o=i0;o<6*D_*6*D_;o+=stride){ int j=o/(6*D_); int k=o-j*6*D_; g_WbgintT[o]=Wbgint[k*6*D_+j]; }
  for (int o=i0;o<6*D_*2*D_;o+=stride){ int j=o/(2*D_); int k=o-j*2*D_; g_WhisintT[o]=Whisint[k*6*D_+j]; }
  for (int o=i0;o<4*D_*10*D_;o+=stride){ int j=o/(10*D_); int k=o-j*10*D_; g_WinmapT[o]=Winmap[k*4*D_+j]; }
  for (int o=i0;o<3*D_*4*D_;o+=stride){ int j=o/(4*D_); int k=o-j*4*D_; g_WihT[o]=Wih[k*3*D_+j]; }
  for (int o=i0;o<3*D_*D_; o+=stride){ int j=o/D_;    int k=o-j*D_;    g_WhhT[o]=Whh[k*3*D_+j]; }
}

// ---------------- packed f32x2 helpers ----------------
__device__ __forceinline__ void ffma2(unsigned long long& a, unsigned long long x, unsigned long long w){
  asm("fma.rn.f32x2 %0, %1, %2, %0;" : "+l"(a) : "l"(x), "l"(w));
}
__device__ __forceinline__ float upsum(unsigned long long a){
  float lo, hi;
  asm("mov.b64 {%0,%1}, %2;" : "=f"(lo), "=f"(hi) : "l"(a));
  return lo + hi;
}

struct __align__(16) Smem {
  // float4 / ulonglong2 accessed arrays (all sizes multiples of 4 floats)
  float h[D_];
  float v[2*D_];
  float x10[10*D_];          // [peer(384) | v*r(128) | v*(1-r)(128)]
  float all_hv[SEE_*3*D_];
  float q[H_*D_];
  float kk[H_*SEE_*D_];
  float bg_atts[6*D_];
  float his_atts[2*D_];
  float gru_in[4*D_];
  float gx[3*D_];
  float gh[3*D_];
  float hbuf[(T_+1)*D_];
  float vbuf[(T_+1)*2*D_];
  // scalar-accessed
  float bg_r[SEE_];
  float logit[H_*SEE_];
  float att[H_*SEE_];
  float ws[SEE_];
  float sc[T_+1];
  float pr[T_+1];
  float pn[T_+1];
  float rbuf[T_+1];
  float red[8];
  float dw0, dw1;
};

__device__ __forceinline__ float sigmoidf_(float x){ return 1.0f/(1.0f+expf(-x)); }

__global__ void __launch_bounds__(NT,1) cokt_kernel(
  const int* __restrict__ prob_id, const int* __restrict__ skills,
  const int* __restrict__ response, const int* __restrict__ bg_index,
  const int* __restrict__ mem_prob_ids, const int* __restrict__ mem_resp,
  const int* __restrict__ mem_concepts,
  const float* __restrict__ states_mem, const float* __restrict__ concept_emb,
  const float* __restrict__ prob_emb,
  const float* __restrict__ W_pred, const float* __restrict__ b_pred,
  const float* __restrict__ b_ih, const float* __restrict__ b_hh,
  const float* __restrict__ b_batch, const float* __restrict__ b_bg,
  const float* __restrict__ b_bgint, const float* __restrict__ b_hisint,
  const float* __restrict__ b_inmap,
  const float* __restrict__ dir_w, const float* __restrict__ heads_map,
  float* __restrict__ out)
{
  extern __shared__ unsigned char smraw[];
  Smem* sm = reinterpret_cast<Smem*>(smraw);
  const int b    = blockIdx.x;
  const int tid  = threadIdx.x;
  const int lane = tid & 31;
  const int wid  = tid >> 5;

  if (tid < D_){ sm->h[tid] = 0.f; sm->hbuf[tid] = 0.f; }
  if (tid >= D_ && tid < 3*D_) sm->vbuf[tid - D_] = 0.f;
  if (tid == NT-1){
    sm->rbuf[0] = 0.f;
    float w0 = dir_w[0], w1 = dir_w[1];
    float m  = fmaxf(w0, w1);
    float e0 = expf(w0 - m), e1 = expf(w1 - m);
    sm->dw0 = e0/(e0+e1); sm->dw1 = e1/(e0+e1);
  }
  __syncthreads();

  const float inv_s192 = 1.0f/sqrtf(192.0f);
  const float inv_s128 = 1.0f/sqrtf(128.0f);

  for (int t = 0; t < T_; ++t){
    const int   pid   = prob_id[t*B_ + b];
    const float respf = (float)response[t*B_ + b];

    // ============ S1: v + bg gather ============
    if (tid < 2*D_){
      int d = tid & (D_-1);
      if (tid < D_){
        float s = 0.f; int cnt = 0;
        #pragma unroll
        for (int c = 0; c < C_; ++c){
          int k = skills[(t*B_ + b)*C_ + c];
          if (k > 0){ s += concept_emb[(size_t)(k-1)*D_ + d]; cnt++; }
        }
        sm->v[d] = s / (cnt ? (float)cnt : 1.f);
      } else {
        sm->v[D_ + d] = (pid > 0) ? prob_emb[(size_t)(pid-1)*D_ + d] : 0.f;
      }
    }
    for (int i = tid; i < SEE_*3*D_; i += NT){
      int s = i / (3*D_);
      int k = i - s*3*D_;
      int idx = bg_index[(t*B_ + b)*R_ + s];
      float val;
      if (k < D_){
        val = states_mem[(size_t)idx*D_ + k];
      } else if (k < 2*D_){
        int d = k - D_;
        float ss = 0.f; int cnt = 0;
        #pragma unroll
        for (int c = 0; c < C_; ++c){
          int kc = mem_concepts[(size_t)idx*C_ + c];
          if (kc > 0){ ss += concept_emb[(size_t)(kc-1)*D_ + d]; cnt++; }
        }
        val = ss / (cnt ? (float)cnt : 1.f);
      } else {
        int d  = k - 2*D_;
        int mp = mem_prob_ids[idx];
        val = (mp > 0) ? prob_emb[(size_t)(mp-1)*D_ + d] : 0.f;
      }
      sm->all_hv[i] = val;
    }
    if (tid >= NT - SEE_){
      int s   = tid - (NT - SEE_);
      int idx = bg_index[(t*B_ + b)*R_ + s];
      sm->bg_r[s] = (float)mem_resp[idx];
    }
    __syncthreads();

    // ============ S2: kk (0..255) | q (256..511), transposed rows + f32x2 ============
    if (tid < H_*D_){
      int hh = tid >> 6, d = tid & 63;
      const ulonglong2* Wg = reinterpret_cast<const ulonglong2*>(
          g_WbgT + (size_t)(hh*D_ + d)*3*D_);
      unsigned long long acc[SEE_];
      #pragma unroll
      for (int s = 0; s < SEE_; ++s) acc[s] = 0ull;
      #pragma unroll 4
      for (int k4 = 0; k4 < 48; ++k4){
        ulonglong2 w = Wg[k4];
        #pragma unroll
        for (int s = 0; s < SEE_; ++s){
          ulonglong2 hv = reinterpret_cast<const ulonglong2*>(sm->all_hv + s*3*D_)[k4];
          ffma2(acc[s], hv.x, w.x);
          ffma2(acc[s], hv.y, w.y);
        }
      }
      float bb = b_bg[hh*D_ + d];
      #pragma unroll
      for (int s = 0; s < SEE_; ++s)
        sm->kk[(hh*SEE_ + s)*D_ + d] = bb + upsum(acc[s]);
    } else {
      int u  = tid - H_*D_;
      int hh = u >> 6, d = u & 63;
      const ulonglong2* Wb = reinterpret_cast<const ulonglong2*>(
          g_WbatchT + (size_t)(hh*D_ + d)*3*D_);
      unsigned long long a0 = 0ull, a1 = 0ull;
      const ulonglong2* hp = reinterpret_cast<const ulonglong2*>(sm->h);
      #pragma unroll
      for (int k = 0; k < 16; ++k){
        ulonglong2 w = Wb[k], x = hp[k];
        ffma2(a0, x.x, w.x); ffma2(a1, x.y, w.y);
      }
      const ulonglong2* vp = reinterpret_cast<const ulonglong2*>(sm->v);
      #pragma unroll
      for (int k = 0; k < 32; ++k){
        ulonglong2 w = Wb[16+k], x = vp[k];
        ffma2(a0, x.x, w.x); ffma2(a1, x.y, w.y);
      }
      sm->q[u] = b_batch[hh*D_ + d] + upsum(a0) + upsum(a1);
    }
    __syncthreads();

    // ============ S3: attention logits ============
    for (int p = wid; p < H_*SEE_; p += NT/32){
      int hh = p / SEE_;
      float a = sm->kk[p*D_ + lane]      * sm->q[hh*D_ + lane]
              + sm->kk[p*D_ + 32 + lane] * sm->q[hh*D_ + 32 + lane];
      #pragma unroll
      for (int o = 16; o; o >>= 1) a += __shfl_xor_sync(0xffffffffu, a, o);
      if (lane == 0) sm->logit[p] = a * inv_s192;
    }
    __syncthreads();

    // ============ S4: att softmax (0..3) | history scores (warps 1..15) ============
    if (tid < H_){
      float mx = -1e30f;
      #pragma unroll
      for (int s = 0; s < SEE_; ++s) mx = fmaxf(mx, sm->logit[tid*SEE_ + s]);
      float sum = 0.f;
      #pragma unroll
      for (int s = 0; s < SEE_; ++s){
        float e = expf(sm->logit[tid*SEE_ + s] - mx);
        sm->att[tid*SEE_ + s] = e; sum += e;
      }
      float inv = 1.f/sum;
      #pragma unroll
      for (int s = 0; s < SEE_; ++s) sm->att[tid*SEE_ + s] *= inv;
    }
    if (wid >= 1){
      float4 myv = reinterpret_cast<const float4*>(sm->v)[lane];
      for (int j = wid-1; j <= t; j += (NT/32)-1){
        float4 x = reinterpret_cast<const float4*>(sm->vbuf + j*2*D_)[lane];
        float a = myv.x*x.x + myv.y*x.y + myv.z*x.z + myv.w*x.w;
        #pragma unroll
        for (int o = 16; o; o >>= 1) a += __shfl_xor_sync(0xffffffffu, a, o);
        if (lane == 0) sm->sc[j] = a * inv_s128;
      }
    }
    __syncthreads();

    // ============ S5: history softmax (warp 0) | ws (warp 1) ============
    if (wid == 0){
      float mx = -1e30f;
      for (int j = lane; j <= t; j += 32) mx = fmaxf(mx, sm->sc[j]);
      #pragma unroll
      for (int o = 16; o; o >>= 1) mx = fmaxf(mx, __shfl_xor_sync(0xffffffffu, mx, o));
      float sum = 0.f;
      for (int j = lane; j <= t; j += 32){
        float e = expf(sm->sc[j] - mx); sm->sc[j] = e; sum += e;
      }
      #pragma unroll
      for (int o = 16; o; o >>= 1) sum += __shfl_xor_sync(0xffffffffu, sum, o);
      float inv = 1.f/sum;
      for (int j = lane; j <= t; j += 32){
        float p  = sm->sc[j]*inv;
        float rb = sm->rbuf[j];
        sm->pr[j] = p*rb; sm->pn[j] = p*(1.f-rb);
      }
    } else if (wid == 1 && lane < SEE_){
      float a = 0.f;
      #pragma unroll
      for (int hh = 0; hh < H_; ++hh) a += heads_map[hh]*sm->att[hh*SEE_ + lane];
      sm->ws[lane] = a;
    }
    __syncthreads();

    // ============ S6: bg_atts (0..383) | his_atts (384..511) ============
    if (tid < 6*D_){
      bool lo  = tid < 3*D_;
      int kidx = lo ? tid : tid - 3*D_;
      float acc = 0.f;
      #pragma unroll
      for (int s = 0; s < SEE_; ++s){
        float r = sm->bg_r[s];
        float f = sm->all_hv[s*3*D_ + kidx] * (lo ? r : (1.f - r));
        acc += sm->ws[s]*f;
      }
      sm->bg_atts[tid] = acc;
    } else {
      int u = tid - 6*D_;
      int d = u & 63;
      const float* w = (u < D_) ? sm->pr : sm->pn;
      float a0 = 0.f, a1 = 0.f;
      int j = 0;
      for (; j + 1 <= t; j += 2){
        a0 += w[j]  *sm->hbuf[j*D_ + d];
        a1 += w[j+1]*sm->hbuf[(j+1)*D_ + d];
      }
      if (j <= t) a0 += w[j]*sm->hbuf[j*D_ + d];
      sm->his_atts[u] = a0 + a1;
    }
    __syncthreads();

    // ============ S7: peer -> x10[0..383] (0..383) | v_resp -> x10[384..639] ============
    if (tid < 6*D_){
      const ulonglong2* Wb = reinterpret_cast<const ulonglong2*>(g_WbgintT  + (size_t)tid*6*D_);
      const ulonglong2* Wh = reinterpret_cast<const ulonglong2*>(g_WhisintT + (size_t)tid*2*D_);
      const ulonglong2* xb = reinterpret_cast<const ulonglong2*>(sm->bg_atts);
      const ulonglong2* xh = reinterpret_cast<const ulonglong2*>(sm->his_atts);
      unsigned long long a0 = 0ull, a1 = 0ull;
      #pragma unroll 8
      for (int k = 0; k < 96; ++k){
        ulonglong2 w = Wb[k], x = xb[k];
        ffma2(a0, x.x, w.x); ffma2(a1, x.y, w.y);
      }
      unsigned long long b0 = 0ull, b1 = 0ull;
      #pragma unroll
      for (int k = 0; k < 32; ++k){
        ulonglong2 w = Wh[k], x = xh[k];
        ffma2(b0, x.x, w.x); ffma2(b1, x.y, w.y);
      }
      float A = b_bgint[tid]  + upsum(a0) + upsum(a1);
      float Bv= b_hisint[tid] + upsum(b0) + upsum(b1);
      sm->x10[tid] = sm->dw0*A + sm->dw1*Bv;
    } else {
      int u = tid - 6*D_;  // 0..127
      float vv = sm->v[u];
      sm->x10[6*D_ + u]        = vv*respf;
      sm->x10[6*D_ + 2*D_ + u] = vv*(1.f - respf);
    }
    __syncthreads();

    // ============ S8: gru_in (0..255) | prob partials (256..511) ============
    if (tid < 4*D_){
      const ulonglong2* W = reinterpret_cast<const ulonglong2*>(g_WinmapT + (size_t)tid*10*D_);
      const ulonglong2* x = reinterpret_cast<const ulonglong2*>(sm->x10);
      unsigned long long a0 = 0ull, a1 = 0ull;
      #pragma unroll 8
      for (int k = 0; k < 160; ++k){
        ulonglong2 w = W[k], xx = x[k];
        ffma2(a0, xx.x, w.x); ffma2(a1, xx.y, w.y);
      }
      sm->gru_in[tid] = b_inmap[tid] + upsum(a0) + upsum(a1);
    } else {
      int u = tid - 4*D_;   // 0..255
      float part = 0.f;
      for (int i = u; i < 9*D_; i += 4*D_){
        float xv = (i < 6*D_) ? sm->x10[i]
                 : ((i < 8*D_) ? sm->v[i - 6*D_] : sm->h[i - 8*D_]);
        part += xv*W_pred[i];
      }
      #pragma unroll
      for (int o = 16; o; o >>= 1) part += __shfl_xor_sync(0xffffffffu, part, o);
      if (lane == 0) sm->red[wid - 8] = part;
    }
    __syncthreads();

    // ============ S9: gx/gh (0..191) | prob finalize (192) ============
    if (tid < 3*D_){
      const ulonglong2* Wi = reinterpret_cast<const ulonglong2*>(g_WihT + (size_t)tid*4*D_);
      const ulonglong2* xg = reinterpret_cast<const ulonglong2*>(sm->gru_in);
      unsigned long long a0 = 0ull, a1 = 0ull;
      #pragma unroll 8
      for (int k = 0; k < 64; ++k){
        ulonglong2 w = Wi[k], x = xg[k];
        ffma2(a0, x.x, w.x); ffma2(a1, x.y, w.y);
      }
      const ulonglong2* Wx = reinterpret_cast<const ulonglong2*>(g_WhhT + (size_t)tid*D_);
      const ulonglong2* hp = reinterpret_cast<const ulonglong2*>(sm->h);
      unsigned long long g0 = 0ull, g1 = 0ull;
      #pragma unroll
      for (int k = 0; k < 16; ++k){
        ulonglong2 w = Wx[k], x = hp[k];
        ffma2(g0, x.x, w.x); ffma2(g1, x.y, w.y);
      }
      sm->gx[tid] = b_ih[tid] + upsum(a0) + upsum(a1);
      sm->gh[tid] = b_hh[tid] + upsum(g0) + upsum(g1);
    } else if (tid == 3*D_){
      float s = b_pred[0];
      #pragma unroll
      for (int i = 0; i < 8; ++i) s += sm->red[i];
      out[b*T_ + t] = s;
    }
    __syncthreads();

    // ============ S10: GRU update + append history ============
    if (tid < D_){
      float r  = sigmoidf_(sm->gx[tid]        + sm->gh[tid]);
      float z  = sigmoidf_(sm->gx[D_   + tid] + sm->gh[D_   + tid]);
      float n  = tanhf   (sm->gx[2*D_ + tid]  + r*sm->gh[2*D_ + tid]);
      float nh = (1.f - z)*n + z*sm->h[tid];
      sm->h[tid] = nh;
      sm->hbuf[(size_t)(t+1)*D_ + tid] = nh;
    } else if (tid < 3*D_){
      int u = tid - D_;
      sm->vbuf[(size_t)(t+1)*2*D_ + u] = sm->v[u];
    } else if (tid == 3*D_){
      sm->rbuf[t+1] = respf;
    }
    __syncthreads();
  }
}

extern "C" void kernel_launch(void* const* d_in, const int* in_sizes, int n_in,
                              void* d_out, int out_size)
{
  (void)in_sizes; (void)n_in; (void)out_size;
  // transpose weights into __device__ scratch (deterministic, graph-capturable)
  prep_kernel<<<256, 256>>>(
    (const float*)d_in[18], // W_bg
    (const float*)d_in[16], // W_batch
    (const float*)d_in[20], // W_bgint
    (const float*)d_in[22], // W_hisint
    (const float*)d_in[24], // W_inmap
    (const float*)d_in[12], // W_ih
    (const float*)d_in[13]);// W_hh

  cudaFuncSetAttribute(cokt_kernel, cudaFuncAttributeMaxDynamicSharedMemorySize,
                       (int)sizeof(Smem));
  cokt_kernel<<<B_, NT, sizeof(Smem)>>>(
    (const int*)  d_in[0],  // prob_id
    (const int*)  d_in[1],  // skills
    (const int*)  d_in[2],  // response
    (const int*)  d_in[3],  // bg_index
    (const int*)  d_in[4],  // mem_prob_ids
    (const int*)  d_in[5],  // mem_resp
    (const int*)  d_in[6],  // mem_concepts
    (const float*)d_in[7],  // states_mem
    (const float*)d_in[8],  // concept_emb
    (const float*)d_in[9],  // prob_emb
    (const float*)d_in[10], // W_pred
    (const float*)d_in[11], // b_pred
    (const float*)d_in[14], // b_ih
    (const float*)d_in[15], // b_hh
    (const float*)d_in[17], // b_batch
    (const float*)d_in[19], // b_bg
    (const float*)d_in[21], // b_bgint
    (const float*)d_in[23], // b_hisint
    (const float*)d_in[25], // b_inmap
    (const float*)d_in[26], // dir_w
    (const float*)d_in[27], // heads_map
    (float*)d_out);
}

// round 11
// speedup vs baseline: 3.0972x; 3.0972x over previous
#include <cuda_runtime.h>
#include <math.h>

#define D_   64
#define T_   128
#define B_   64
#define R_   20
#define SEE_ 10
#define H_   4
#define C_   4
#define NT   512

typedef unsigned long long ull;

__device__ __forceinline__ void ffma2(ull& a, ull x, ull w){
  asm("fma.rn.f32x2 %0, %1, %2, %0;" : "+l"(a) : "l"(x), "l"(w));
}
__device__ __forceinline__ ull pack2(float lo, float hi){
  ull r; asm("mov.b64 %0, {%1,%2};" : "=l"(r) : "f"(lo), "f"(hi)); return r;
}
__device__ __forceinline__ void unpack2(ull a, float& lo, float& hi){
  asm("mov.b64 {%0,%1}, %2;" : "=f"(lo), "=f"(hi) : "l"(a));
}
__device__ __forceinline__ float sigmoidf_(float x){ return 1.0f/(1.0f+expf(-x)); }

struct __align__(16) Smem {
  float h[D_];
  float v[2*D_];
  float x10[10*D_];            // [peer 384 | v*r 128 | v*(1-r) 128]
  float hvT[192*12];           // all_hv transposed: [k][s], padded to 12
  float q[H_*D_];
  float kk[H_*SEE_*D_];
  float bg_atts[6*D_];
  float his_atts[2*D_];
  float gru_in[4*D_];
  float gx[3*D_];
  float gh[3*D_];
  float hbuf[(T_+1)*D_];
  float vbuf[(T_+1)*2*D_];
  ull   part[512];             // phase-local partial sums (reused)
  float bg_r[SEE_];
  float logit[H_*SEE_];
  float att[H_*SEE_];
  float ws[SEE_];
  float sc[T_+1];
  float pr[T_+1];
  float pn[T_+1];
  float rbuf[T_+1];
  float dw0, dw1;
};

__global__ void __launch_bounds__(NT,1) cokt_kernel(
  const int* __restrict__ prob_id, const int* __restrict__ skills,
  const int* __restrict__ response, const int* __restrict__ bg_index,
  const int* __restrict__ mem_prob_ids, const int* __restrict__ mem_resp,
  const int* __restrict__ mem_concepts,
  const float* __restrict__ states_mem, const float* __restrict__ concept_emb,
  const float* __restrict__ prob_emb,
  const float* __restrict__ W_pred, const float* __restrict__ b_pred,
  const float* __restrict__ W_ih, const float* __restrict__ W_hh,
  const float* __restrict__ b_ih, const float* __restrict__ b_hh,
  const float* __restrict__ W_batch, const float* __restrict__ b_batch,
  const float* __restrict__ W_bg, const float* __restrict__ b_bg,
  const float* __restrict__ W_bgint, const float* __restrict__ b_bgint,
  const float* __restrict__ W_hisint, const float* __restrict__ b_hisint,
  const float* __restrict__ W_inmap, const float* __restrict__ b_inmap,
  const float* __restrict__ dir_w, const float* __restrict__ heads_map,
  float* __restrict__ out)
{
  extern __shared__ unsigned char smraw[];
  Smem* sm = reinterpret_cast<Smem*>(smraw);
  const int b    = blockIdx.x;
  const int tid  = threadIdx.x;
  const int lane = tid & 31;
  const int wid  = tid >> 5;

  if (tid < D_){ sm->h[tid] = 0.f; sm->hbuf[tid] = 0.f; }
  if (tid >= D_ && tid < 3*D_) sm->vbuf[tid - D_] = 0.f;
  if (tid == NT-1){
    sm->rbuf[0] = 0.f;
    float w0 = dir_w[0], w1 = dir_w[1];
    float m  = fmaxf(w0, w1);
    float e0 = expf(w0 - m), e1 = expf(w1 - m);
    sm->dw0 = e0/(e0+e1); sm->dw1 = e1/(e0+e1);
  }
  __syncthreads();

  const float inv_s192 = 1.0f/sqrtf(192.0f);
  const float inv_s128 = 1.0f/sqrtf(128.0f);

  for (int t = 0; t < T_; ++t){
    const int   pid   = prob_id[t*B_ + b];
    const float respf = (float)response[t*B_ + b];

    // ============ S1: v + bg gather (writes hvT [k][s]) ============
    if (tid < 2*D_){
      int d = tid & (D_-1);
      if (tid < D_){
        float s = 0.f; int cnt = 0;
        #pragma unroll
        for (int c = 0; c < C_; ++c){
          int k = skills[(t*B_ + b)*C_ + c];
          if (k > 0){ s += concept_emb[(size_t)(k-1)*D_ + d]; cnt++; }
        }
        sm->v[d] = s / (cnt ? (float)cnt : 1.f);
      } else {
        sm->v[D_ + d] = (pid > 0) ? prob_emb[(size_t)(pid-1)*D_ + d] : 0.f;
      }
    }
    for (int i = tid; i < SEE_*3*D_; i += NT){
      int s = i / (3*D_);
      int k = i - s*3*D_;
      int idx = bg_index[(t*B_ + b)*R_ + s];
      float val;
      if (k < D_){
        val = states_mem[(size_t)idx*D_ + k];
      } else if (k < 2*D_){
        int d = k - D_;
        float ss = 0.f; int cnt = 0;
        #pragma unroll
        for (int c = 0; c < C_; ++c){
          int kc = mem_concepts[(size_t)idx*C_ + c];
          if (kc > 0){ ss += concept_emb[(size_t)(kc-1)*D_ + d]; cnt++; }
        }
        val = ss / (cnt ? (float)cnt : 1.f);
      } else {
        int d  = k - 2*D_;
        int mp = mem_prob_ids[idx];
        val = (mp > 0) ? prob_emb[(size_t)(mp-1)*D_ + d] : 0.f;
      }
      sm->hvT[k*12 + s] = val;
    }
    if (tid >= NT - SEE_){
      int s   = tid - (NT - SEE_);
      int idx = bg_index[(t*B_ + b)*R_ + s];
      sm->bg_r[s] = (float)mem_resp[idx];
    }
    __syncthreads();

    // ============ S2: kk (0..255) | q (256..383) | v_resp (384..511) ============
    if (tid < H_*D_){
      int hh = tid >> 6, d = tid & 63;
      const float* Wg = W_bg + (size_t)hh*(3*D_*D_) + d;   // + k*64, coalesced over d
      ull a0=0,a1=0,a2=0,a3=0,a4=0;
      #pragma unroll 2
      for (int k0 = 0; k0 < 192; k0 += 8){
        float w[8];
        #pragma unroll
        for (int u = 0; u < 8; ++u) w[u] = Wg[(size_t)(k0+u)*64];
        #pragma unroll
        for (int u = 0; u < 8; ++u){
          ull ww = pack2(w[u], w[u]);
          const ull* hv = reinterpret_cast<const ull*>(sm->hvT + (k0+u)*12);
          ffma2(a0, hv[0], ww); ffma2(a1, hv[1], ww); ffma2(a2, hv[2], ww);
          ffma2(a3, hv[3], ww); ffma2(a4, hv[4], ww);
        }
      }
      float bb = b_bg[hh*64 + d];
      float lo, hi;
      unpack2(a0, lo, hi); sm->kk[(hh*10+0)*64+d] = bb+lo; sm->kk[(hh*10+1)*64+d] = bb+hi;
      unpack2(a1, lo, hi); sm->kk[(hh*10+2)*64+d] = bb+lo; sm->kk[(hh*10+3)*64+d] = bb+hi;
      unpack2(a2, lo, hi); sm->kk[(hh*10+4)*64+d] = bb+lo; sm->kk[(hh*10+5)*64+d] = bb+hi;
      unpack2(a3, lo, hi); sm->kk[(hh*10+6)*64+d] = bb+lo; sm->kk[(hh*10+7)*64+d] = bb+hi;
      unpack2(a4, lo, hi); sm->kk[(hh*10+8)*64+d] = bb+lo; sm->kk[(hh*10+9)*64+d] = bb+hi;
    } else if (tid < 384){
      int u  = tid - 256;
      int hh = u >> 5, dp = u & 31;
      const ull* Wb = reinterpret_cast<const ull*>(W_batch + (size_t)hh*(3*D_*D_)) + dp; // + k*32
      ull acc = 0;
      const float4* xh_ = reinterpret_cast<const float4*>(sm->h);
      #pragma unroll 2
      for (int k4 = 0; k4 < 16; ++k4){
        float4 x = xh_[k4]; int k = k4*4;
        ull w0 = Wb[(size_t)(k+0)*32], w1 = Wb[(size_t)(k+1)*32];
        ull w2 = Wb[(size_t)(k+2)*32], w3 = Wb[(size_t)(k+3)*32];
        ffma2(acc, pack2(x.x,x.x), w0); ffma2(acc, pack2(x.y,x.y), w1);
        ffma2(acc, pack2(x.z,x.z), w2); ffma2(acc, pack2(x.w,x.w), w3);
      }
      const float4* xv_ = reinterpret_cast<const float4*>(sm->v);
      #pragma unroll 2
      for (int k4 = 0; k4 < 32; ++k4){
        float4 x = xv_[k4]; int k = 64 + k4*4;
        ull w0 = Wb[(size_t)(k+0)*32], w1 = Wb[(size_t)(k+1)*32];
        ull w2 = Wb[(size_t)(k+2)*32], w3 = Wb[(size_t)(k+3)*32];
        ffma2(acc, pack2(x.x,x.x), w0); ffma2(acc, pack2(x.y,x.y), w1);
        ffma2(acc, pack2(x.z,x.z), w2); ffma2(acc, pack2(x.w,x.w), w3);
      }
      float lo, hi; unpack2(acc, lo, hi);
      sm->q[hh*64 + 2*dp]     = b_batch[hh*64 + 2*dp]     + lo;
      sm->q[hh*64 + 2*dp + 1] = b_batch[hh*64 + 2*dp + 1] + hi;
    } else {
      int u = tid - 384;                 // 0..127
      float vv = sm->v[u];
      sm->x10[6*D_ + u]        = vv*respf;
      sm->x10[6*D_ + 2*D_ + u] = vv*(1.f - respf);
    }
    __syncthreads();

    // ============ S3: attention logits ============
    for (int p = wid; p < H_*SEE_; p += NT/32){
      int hh = p / SEE_;
      float a = sm->kk[p*D_ + lane]      * sm->q[hh*D_ + lane]
              + sm->kk[p*D_ + 32 + lane] * sm->q[hh*D_ + 32 + lane];
      #pragma unroll
      for (int o = 16; o; o >>= 1) a += __shfl_xor_sync(0xffffffffu, a, o);
      if (lane == 0) sm->logit[p] = a * inv_s192;
    }
    __syncthreads();

    // ============ S4: att softmax (0..3) | history scores (warps 1..15) ============
    if (tid < H_){
      float mx = -1e30f;
      #pragma unroll
      for (int s = 0; s < SEE_; ++s) mx = fmaxf(mx, sm->logit[tid*SEE_ + s]);
      float sum = 0.f;
      #pragma unroll
      for (int s = 0; s < SEE_; ++s){
        float e = expf(sm->logit[tid*SEE_ + s] - mx);
        sm->att[tid*SEE_ + s] = e; sum += e;
      }
      float inv = 1.f/sum;
      #pragma unroll
      for (int s = 0; s < SEE_; ++s) sm->att[tid*SEE_ + s] *= inv;
    }
    if (wid >= 1){
      float4 myv = reinterpret_cast<const float4*>(sm->v)[lane];
      for (int j = wid-1; j <= t; j += (NT/32)-1){
        float4 x = reinterpret_cast<const float4*>(sm->vbuf + j*2*D_)[lane];
        float a = myv.x*x.x + myv.y*x.y + myv.z*x.z + myv.w*x.w;
        #pragma unroll
        for (int o = 16; o; o >>= 1) a += __shfl_xor_sync(0xffffffffu, a, o);
        if (lane == 0) sm->sc[j] = a * inv_s128;
      }
    }
    __syncthreads();

    // ============ S5: history softmax (warp 0) | ws (warp 1) ============
    if (wid == 0){
      float mx = -1e30f;
      for (int j = lane; j <= t; j += 32) mx = fmaxf(mx, sm->sc[j]);
      #pragma unroll
      for (int o = 16; o; o >>= 1) mx = fmaxf(mx, __shfl_xor_sync(0xffffffffu, mx, o));
      float sum = 0.f;
      for (int j = lane; j <= t; j += 32){
        float e = expf(sm->sc[j] - mx); sm->sc[j] = e; sum += e;
      }
      #pragma unroll
      for (int o = 16; o; o >>= 1) sum += __shfl_xor_sync(0xffffffffu, sum, o);
      float inv = 1.f/sum;
      for (int j = lane; j <= t; j += 32){
        float p  = sm->sc[j]*inv;
        float rb = sm->rbuf[j];
        sm->pr[j] = p*rb; sm->pn[j] = p*(1.f-rb);
      }
    } else if (wid == 1 && lane < SEE_){
      float a = 0.f;
      #pragma unroll
      for (int hh = 0; hh < H_; ++hh) a += heads_map[hh]*sm->att[hh*SEE_ + lane];
      sm->ws[lane] = a;
    }
    __syncthreads();

    // ============ S6: bg_atts (0..383) | his_atts (384..511) ============
    if (tid < 6*D_){
      bool lo  = tid < 3*D_;
      int kidx = lo ? tid : tid - 3*D_;
      float acc = 0.f;
      #pragma unroll
      for (int s = 0; s < SEE_; ++s){
        float r = sm->bg_r[s];
        float f = sm->hvT[kidx*12 + s] * (lo ? r : (1.f - r));
        acc += sm->ws[s]*f;
      }
      sm->bg_atts[tid] = acc;
    } else {
      int u = tid - 6*D_;
      int d = u & 63;
      const float* w = (u < D_) ? sm->pr : sm->pn;
      float a0 = 0.f, a1 = 0.f;
      int j = 0;
      for (; j + 1 <= t; j += 2){
        a0 += w[j]  *sm->hbuf[j*D_ + d];
        a1 += w[j+1]*sm->hbuf[(j+1)*D_ + d];
      }
      if (j <= t) a0 += w[j]*sm->hbuf[j*D_ + d];
      sm->his_atts[u] = a0 + a1;
    }
    __syncthreads();

    // ============ S7: peer partials (0..383, 2 k-segs) -> combine ============
    if (tid < 384){
      int seg = (tid >= 192);
      int jp  = tid - seg*192;
      const ull* Wb = reinterpret_cast<const ull*>(W_bgint)  + jp;  // + k*192
      const ull* Wh = reinterpret_cast<const ull*>(W_hisint) + jp;  // + k*192
      const float4* xb = reinterpret_cast<const float4*>(sm->bg_atts)  + seg*48;
      const float4* xh = reinterpret_cast<const float4*>(sm->his_atts) + seg*16;
      const int kb0 = seg*192, kh0 = seg*64;
      ull accA = 0, accB = 0;
      #pragma unroll 2
      for (int k4 = 0; k4 < 48; ++k4){
        float4 x = xb[k4]; int k = kb0 + k4*4;
        ull w0 = Wb[(size_t)(k+0)*192], w1 = Wb[(size_t)(k+1)*192];
        ull w2 = Wb[(size_t)(k+2)*192], w3 = Wb[(size_t)(k+3)*192];
        ffma2(accA, pack2(x.x,x.x), w0); ffma2(accA, pack2(x.y,x.y), w1);
        ffma2(accA, pack2(x.z,x.z), w2); ffma2(accA, pack2(x.w,x.w), w3);
      }
      #pragma unroll 2
      for (int k4 = 0; k4 < 16; ++k4){
        float4 x = xh[k4]; int k = kh0 + k4*4;
        ull w0 = Wh[(size_t)(k+0)*192], w1 = Wh[(size_t)(k+1)*192];
        ull w2 = Wh[(size_t)(k+2)*192], w3 = Wh[(size_t)(k+3)*192];
        ffma2(accB, pack2(x.x,x.x), w0); ffma2(accB, pack2(x.y,x.y), w1);
        ffma2(accB, pack2(x.z,x.z), w2); ffma2(accB, pack2(x.w,x.w), w3);
      }
      float Al,Ah,Bl,Bh; unpack2(accA,Al,Ah); unpack2(accB,Bl,Bh);
      sm->part[seg*192 + jp] = pack2(sm->dw0*Al + sm->dw1*Bl,
                                     sm->dw0*Ah + sm->dw1*Bh);
    }
    __syncthreads();
    if (tid < 192){
      float l0,h0,l1,h1;
      unpack2(sm->part[tid],       l0, h0);
      unpack2(sm->part[192 + tid], l1, h1);
      int j = 2*tid;
      float bl = sm->dw0*b_bgint[j]   + sm->dw1*b_hisint[j];
      float bh = sm->dw0*b_bgint[j+1] + sm->dw1*b_hisint[j+1];
      sm->x10[j]   = bl + l0 + l1;
      sm->x10[j+1] = bh + h0 + h1;
    }
    __syncthreads();

    // ============ S8: gru_in partials (all 512, 4 k-segs) -> combine ============
    {
      int seg = tid >> 7, jp = tid & 127;
      const ull* W = reinterpret_cast<const ull*>(W_inmap) + jp;   // + k*128
      const float4* xv = reinterpret_cast<const float4*>(sm->x10) + seg*40;
      const int k0 = seg*160;
      ull acc = 0;
      #pragma unroll 2
      for (int k4 = 0; k4 < 40; ++k4){
        float4 x = xv[k4]; int k = k0 + k4*4;
        ull w0 = W[(size_t)(k+0)*128], w1 = W[(size_t)(k+1)*128];
        ull w2 = W[(size_t)(k+2)*128], w3 = W[(size_t)(k+3)*128];
        ffma2(acc, pack2(x.x,x.x), w0); ffma2(acc, pack2(x.y,x.y), w1);
        ffma2(acc, pack2(x.z,x.z), w2); ffma2(acc, pack2(x.w,x.w), w3);
      }
      sm->part[seg*128 + jp] = acc;
    }
    __syncthreads();
    if (tid < 128){
      float l0,h0,l1,h1,l2,h2,l3,h3;
      unpack2(sm->part[tid],        l0,h0);
      unpack2(sm->part[128 + tid],  l1,h1);
      unpack2(sm->part[256 + tid],  l2,h2);
      unpack2(sm->part[384 + tid],  l3,h3);
      int j = 2*tid;
      sm->gru_in[j]   = b_inmap[j]   + l0+l1+l2+l3;
      sm->gru_in[j+1] = b_inmap[j+1] + h0+h1+h2+h3;
    }
    __syncthreads();

    // ============ S9: gx partials (0..383) | gh (384..479) | prob (480..511) ============
    if (tid < 384){
      int seg = tid/96, jp = tid - seg*96;
      const ull* W = reinterpret_cast<const ull*>(W_ih) + jp;      // + k*96
      const float4* xv = reinterpret_cast<const float4*>(sm->gru_in) + seg*16;
      const int k0 = seg*64;
      ull acc = 0;
      #pragma unroll 2
      for (int k4 = 0; k4 < 16; ++k4){
        float4 x = xv[k4]; int k = k0 + k4*4;
        ull w0 = W[(size_t)(k+0)*96], w1 = W[(size_t)(k+1)*96];
        ull w2 = W[(size_t)(k+2)*96], w3 = W[(size_t)(k+3)*96];
        ffma2(acc, pack2(x.x,x.x), w0); ffma2(acc, pack2(x.y,x.y), w1);
        ffma2(acc, pack2(x.z,x.z), w2); ffma2(acc, pack2(x.w,x.w), w3);
      }
      sm->part[seg*96 + jp] = acc;
    } else if (tid < 480){
      int jp = tid - 384;                       // 0..95
      const ull* W = reinterpret_cast<const ull*>(W_hh) + jp;      // + k*96
      const float4* xv = reinterpret_cast<const float4*>(sm->h);
      ull acc = 0;
      #pragma unroll 2
      for (int k4 = 0; k4 < 16; ++k4){
        float4 x = xv[k4]; int k = k4*4;
        ull w0 = W[(size_t)(k+0)*96], w1 = W[(size_t)(k+1)*96];
        ull w2 = W[(size_t)(k+2)*96], w3 = W[(size_t)(k+3)*96];
        ffma2(acc, pack2(x.x,x.x), w0); ffma2(acc, pack2(x.y,x.y), w1);
        ffma2(acc, pack2(x.z,x.z), w2); ffma2(acc, pack2(x.w,x.w), w3);
      }
      float lo, hi; unpack2(acc, lo, hi);
      sm->gh[2*jp]   = b_hh[2*jp]   + lo;
      sm->gh[2*jp+1] = b_hh[2*jp+1] + hi;
    } else {
      int l = tid - 480;                        // 0..31
      float part = 0.f;
      #pragma unroll
      for (int i0 = 0; i0 < 9*D_; i0 += 32){
        int i = i0 + l;
        float xv = (i < 6*D_) ? sm->x10[i]
                 : ((i < 8*D_) ? sm->v[i - 6*D_] : sm->h[i - 8*D_]);
        part += xv * W_pred[i];
      }
      #pragma unroll
      for (int o = 16; o; o >>= 1) part += __shfl_xor_sync(0xffffffffu, part, o);
      if (l == 0) out[b*T_ + t] = part + b_pred[0];
    }
    __syncthreads();
    if (tid < 96){
      float l0,h0,l1,h1,l2,h2,l3,h3;
      unpack2(sm->part[tid],       l0,h0);
      unpack2(sm->part[96 + tid],  l1,h1);
      unpack2(sm->part[192 + tid], l2,h2);
      unpack2(sm->part[288 + tid], l3,h3);
      int j = 2*tid;
      sm->gx[j]   = b_ih[j]   + l0+l1+l2+l3;
      sm->gx[j+1] = b_ih[j+1] + h0+h1+h2+h3;
    }
    __syncthreads();

    // ============ S10: GRU update + append history ============
    if (tid < D_){
      float r  = sigmoidf_(sm->gx[tid]        + sm->gh[tid]);
      float z  = sigmoidf_(sm->gx[D_   + tid] + sm->gh[D_   + tid]);
      float n  = tanhf   (sm->gx[2*D_ + tid]  + r*sm->gh[2*D_ + tid]);
      float nh = (1.f - z)*n + z*sm->h[tid];
      sm->h[tid] = nh;
      sm->hbuf[(size_t)(t+1)*D_ + tid] = nh;
    } else if (tid < 3*D_){
      int u = tid - D_;
      sm->vbuf[(size_t)(t+1)*2*D_ + u] = sm->v[u];
    } else if (tid == 3*D_){
      sm->rbuf[t+1] = respf;
    }
    __syncthreads();
  }
}

extern "C" void kernel_launch(void* const* d_in, const int* in_sizes, int n_in,
                              void* d_out, int out_size)
{
  (void)in_sizes; (void)n_in; (void)out_size;
  cudaFuncSetAttribute(cokt_kernel, cudaFuncAttributeMaxDynamicSharedMemorySize,
                       (int)sizeof(Smem));
  cokt_kernel<<<B_, NT, sizeof(Smem)>>>(
    (const int*)  d_in[0],  // prob_id
    (const int*)  d_in[1],  // skills
    (const int*)  d_in[2],  // response
    (const int*)  d_in[3],  // bg_index
    (const int*)  d_in[4],  // mem_prob_ids
    (const int*)  d_in[5],  // mem_resp
    (const int*)  d_in[6],  // mem_concepts
    (const float*)d_in[7],  // states_mem
    (const float*)d_in[8],  // concept_emb
    (const float*)d_in[9],  // prob_emb
    (const float*)d_in[10], // W_pred
    (const float*)d_in[11], // b_pred
    (const float*)d_in[12], // W_ih
    (const float*)d_in[13], // W_hh
    (const float*)d_in[14], // b_ih
    (const float*)d_in[15], // b_hh
    (const float*)d_in[16], // W_batch
    (const float*)d_in[17], // b_batch
    (const float*)d_in[18], // W_bg
    (const float*)d_in[19], // b_bg
    (const float*)d_in[20], // W_bgint
    (const float*)d_in[21], // b_bgint
    (const float*)d_in[22], // W_hisint
    (const float*)d_in[23], // b_hisint
    (const float*)d_in[24], // W_inmap
    (const float*)d_in[25], // b_inmap
    (const float*)d_in[26], // dir_w
    (const float*)d_in[27], // heads_map
    (float*)d_out);
}

// round 12
// speedup vs baseline: 3.5790x; 1.1556x over previous
#include <cuda_runtime.h>
#include <math.h>

#define D_   64
#define T_   128
#define B_   64
#define R_   20
#define SEE_ 10
#define H_   4
#define C_   4
#define NT   512

typedef unsigned long long ull;

// ---------------- precomputed per-(t,b) data ----------------
__device__ __align__(16) float g_kk [ (size_t)B_*T_*2560 ];  // [(t*B+b)][(h*10+s)*64+d], bias folded
__device__ __align__(16) float g_hv [ (size_t)B_*T_*2304 ];  // [(t*B+b)][k*12+s] (hvT, padded s->12)
__device__ __align__(16) float g_bgr[ (size_t)B_*T_*12 ];    // [(t*B+b)][s]
__device__ __align__(16) float g_qv [ (size_t)B_*T_*256 ];   // v-part of q + b_batch
__device__ __align__(16) float g_v  [ (size_t)B_*(T_+1)*128 ]; // [b][j][0..127], row j = v_{j-1}, row0=0
__device__ __align__(16) float g_pr [ (size_t)B_*T_*132 ];   // softmax(sc)*resp
__device__ __align__(16) float g_pn [ (size_t)B_*T_*132 ];   // softmax(sc)*(1-resp)

// ---------------- helpers ----------------
__device__ __forceinline__ void ffma2(ull& a, ull x, ull w){
  asm("fma.rn.f32x2 %0, %1, %2, %0;" : "+l"(a) : "l"(x), "l"(w));
}
__device__ __forceinline__ ull pack2(float lo, float hi){
  ull r; asm("mov.b64 %0, {%1,%2};" : "=l"(r) : "f"(lo), "f"(hi)); return r;
}
__device__ __forceinline__ void unpack2(ull a, float& lo, float& hi){
  asm("mov.b64 {%0,%1}, %2;" : "=f"(lo), "=f"(hi) : "l"(a));
}
__device__ __forceinline__ float sigmoidf_(float x){ return 1.0f/(1.0f+expf(-x)); }
__device__ __forceinline__ void cp16(void* sdst, const void* gsrc){
  unsigned sa;
  asm("{.reg .u64 t; cvta.to.shared.u64 t, %1; cvt.u32.u64 %0, t;}" : "=r"(sa) : "l"(sdst));
  asm volatile("cp.async.cg.shared.global [%0], [%1], 16;" :: "r"(sa), "l"(gsrc));
}

// ================= K1: bg gather + kk GEMV (grid-parallel over (t,b)) =================
__global__ void __launch_bounds__(256,4) k1_kernel(
  const int* __restrict__ bg_index, const int* __restrict__ mem_prob_ids,
  const int* __restrict__ mem_resp, const int* __restrict__ mem_concepts,
  const float* __restrict__ states_mem, const float* __restrict__ concept_emb,
  const float* __restrict__ prob_emb,
  const float* __restrict__ W_bg, const float* __restrict__ b_bg)
{
  __shared__ __align__(16) float hvT[2304];
  const int tb = blockIdx.x;
  const int t = tb / B_, b = tb - t*B_;
  const int tid = threadIdx.x;

  // zero pads (s=10,11)
  for (int i = tid; i < 192*2; i += 256) hvT[(i>>1)*12 + 10 + (i&1)] = 0.f;
  // gather all_hv -> hvT[k*12+s]
  for (int i = tid; i < SEE_*3*D_; i += 256){
    int s = i / (3*D_);
    int k = i - s*3*D_;
    int idx = bg_index[(t*B_ + b)*R_ + s];
    float val;
    if (k < D_){
      val = states_mem[(size_t)idx*D_ + k];
    } else if (k < 2*D_){
      int d = k - D_;
      float ss = 0.f; int cnt = 0;
      #pragma unroll
      for (int c = 0; c < C_; ++c){
        int kc = mem_concepts[(size_t)idx*C_ + c];
        if (kc > 0){ ss += concept_emb[(size_t)(kc-1)*D_ + d]; cnt++; }
      }
      val = ss / (cnt ? (float)cnt : 1.f);
    } else {
      int d  = k - 2*D_;
      int mp = mem_prob_ids[idx];
      val = (mp > 0) ? prob_emb[(size_t)(mp-1)*D_ + d] : 0.f;
    }
    hvT[k*12 + s] = val;
  }
  if (tid < SEE_){
    int idx = bg_index[(t*B_ + b)*R_ + tid];
    g_bgr[(size_t)tb*12 + tid] = (float)mem_resp[idx];
  }
  __syncthreads();

  // copy hvT out
  for (int i = tid; i < 2304; i += 256)
    g_hv[(size_t)tb*2304 + i] = hvT[i];

  // kk: thread = (h,d)
  {
    int hh = tid >> 6, d = tid & 63;
    const float* Wg = W_bg + (size_t)hh*(3*D_*D_) + d;
    ull a0=0,a1=0,a2=0,a3=0,a4=0;
    #pragma unroll 2
    for (int k0 = 0; k0 < 192; k0 += 8){
      float w[8];
      #pragma unroll
      for (int u = 0; u < 8; ++u) w[u] = Wg[(size_t)(k0+u)*64];
      #pragma unroll
      for (int u = 0; u < 8; ++u){
        ull ww = pack2(w[u], w[u]);
        const ull* hv = reinterpret_cast<const ull*>(hvT + (k0+u)*12);
        ffma2(a0, hv[0], ww); ffma2(a1, hv[1], ww); ffma2(a2, hv[2], ww);
        ffma2(a3, hv[3], ww); ffma2(a4, hv[4], ww);
      }
    }
    float bb = b_bg[hh*64 + d];
    float lo, hi;
    float* o = g_kk + (size_t)tb*2560 + (size_t)hh*10*64 + d;
    unpack2(a0, lo, hi); o[0*64]=bb+lo; o[1*64]=bb+hi;
    unpack2(a1, lo, hi); o[2*64]=bb+lo; o[3*64]=bb+hi;
    unpack2(a2, lo, hi); o[4*64]=bb+lo; o[5*64]=bb+hi;
    unpack2(a3, lo, hi); o[6*64]=bb+lo; o[7*64]=bb+hi;
    unpack2(a4, lo, hi); o[8*64]=bb+lo; o[9*64]=bb+hi;
  }
}

// ================= K2: v + qv (grid over (t,b)) =================
__global__ void __launch_bounds__(128,8) k2_kernel(
  const int* __restrict__ prob_id, const int* __restrict__ skills,
  const float* __restrict__ concept_emb, const float* __restrict__ prob_emb,
  const float* __restrict__ W_batch, const float* __restrict__ b_batch)
{
  __shared__ __align__(16) float v[128];
  const int tb = blockIdx.x;
  const int t = tb / B_, b = tb - t*B_;
  const int tid = threadIdx.x;

  float val;
  if (tid < D_){
    float s = 0.f; int cnt = 0;
    #pragma unroll
    for (int c = 0; c < C_; ++c){
      int k = skills[(t*B_ + b)*C_ + c];
      if (k > 0){ s += concept_emb[(size_t)(k-1)*D_ + tid]; cnt++; }
    }
    val = s / (cnt ? (float)cnt : 1.f);
  } else {
    int pid = prob_id[t*B_ + b];
    val = (pid > 0) ? prob_emb[(size_t)(pid-1)*D_ + (tid - D_)] : 0.f;
  }
  v[tid] = val;
  g_v[((size_t)b*(T_+1) + t + 1)*128 + tid] = val;
  if (t == 0) g_v[((size_t)b*(T_+1))*128 + tid] = 0.f;
  __syncthreads();

  // qv (v-part of q, k = 64..191) + b_batch
  int hh = tid >> 5, dp = tid & 31;
  const ull* Wb = reinterpret_cast<const ull*>(W_batch + (size_t)hh*(3*D_*D_)) + dp;
  ull acc = 0;
  const float4* xv = reinterpret_cast<const float4*>(v);
  #pragma unroll 2
  for (int k4 = 0; k4 < 32; ++k4){
    float4 x = xv[k4]; int k = 64 + k4*4;
    ull w0 = Wb[(size_t)(k+0)*32], w1 = Wb[(size_t)(k+1)*32];
    ull w2 = Wb[(size_t)(k+2)*32], w3 = Wb[(size_t)(k+3)*32];
    ffma2(acc, pack2(x.x,x.x), w0); ffma2(acc, pack2(x.y,x.y), w1);
    ffma2(acc, pack2(x.z,x.z), w2); ffma2(acc, pack2(x.w,x.w), w3);
  }
  float lo, hi; unpack2(acc, lo, hi);
  g_qv[(size_t)tb*256 + hh*64 + 2*dp]     = b_batch[hh*64 + 2*dp]     + lo;
  g_qv[(size_t)tb*256 + hh*64 + 2*dp + 1] = b_batch[hh*64 + 2*dp + 1] + hi;
}

// ================= K3: history softmax weights pr/pn (grid over b) =================
__global__ void __launch_bounds__(512,1) k3_kernel(const int* __restrict__ response)
{
  extern __shared__ float k3s[];           // vv[(T+1)*129] + resp[129]
  float* vv   = k3s;
  float* resp = k3s + (T_+1)*129;
  const int b   = blockIdx.x;
  const int tid = threadIdx.x;
  const int lane = tid & 31, wid = tid >> 5;
  const float inv_s128 = 1.0f/sqrtf(128.0f);

  for (int i = tid; i < (T_+1)*128; i += 512){
    int row = i >> 7, col = i & 127;
    vv[row*129 + col] = g_v[(size_t)b*(T_+1)*128 + i];
  }
  for (int j = tid; j <= T_; j += 512)
    resp[j] = (j == 0) ? 0.f : (float)response[(j-1)*B_ + b];
  __syncthreads();

  for (int t = wid; t < T_; t += 16){
    const float* vt = vv + (t+1)*129;
    float scv[4]; int nj = 0;
    for (int j = lane; j <= t; j += 32){
      const float* vj = vv + j*129;
      float a = 0.f;
      #pragma unroll 4
      for (int k = 0; k < 128; ++k) a += vt[k]*vj[k];
      scv[nj++] = a * inv_s128;
    }
    float mx = -1e30f;
    for (int i = 0; i < nj; ++i) mx = fmaxf(mx, scv[i]);
    #pragma unroll
    for (int o = 16; o; o >>= 1) mx = fmaxf(mx, __shfl_xor_sync(0xffffffffu, mx, o));
    float sum = 0.f;
    for (int i = 0; i < nj; ++i){ scv[i] = expf(scv[i]-mx); sum += scv[i]; }
    #pragma unroll
    for (int o = 16; o; o >>= 1) sum += __shfl_xor_sync(0xffffffffu, sum, o);
    float inv = 1.f/sum;
    int i = 0;
    for (int j = lane; j <= t; j += 32, ++i){
      float p = scv[i]*inv;
      float rb = resp[j];
      g_pr[((size_t)b*T_ + t)*132 + j] = p*rb;
      g_pn[((size_t)b*T_ + t)*132 + j] = p*(1.f-rb);
    }
  }
}

// ================= K4: sequential recurrence =================
struct __align__(16) SmemSeq {
  alignas(16) float h[D_];
  alignas(16) float q[256];
  alignas(16) float his_atts[128];
  alignas(16) float hisP[384];
  alignas(16) float bg_atts[384];
  alignas(16) float x10[640];
  alignas(16) float gru_in[256];
  alignas(16) float gx[192];
  alignas(16) float gh[192];
  alignas(16) float hbuf[(T_+1)*D_];
  alignas(16) ull   part[512];
  alignas(16) float kk[2][2560];
  alignas(16) float hvT[2][2304];
  alignas(16) float v[2][128];
  alignas(16) float qv[2][256];
  alignas(16) float pr[2][132];
  alignas(16) float pn[2][132];
  alignas(16) float bgr[2][12];
  float logit[40], att[40], ws[12];
  float dw0, dw1;
};

__device__ __forceinline__ void do_prefetch(SmemSeq* sm, int b, int tn, int nb,
                                            int idx, int nthr)
{
  size_t tb = (size_t)tn*B_ + b;
  float* d0 = sm->kk[nb];  const float* s0 = g_kk + tb*2560;
  float* d1 = sm->hvT[nb]; const float* s1 = g_hv + tb*2304;
  float* d2 = sm->v[nb];   const float* s2 = g_v  + ((size_t)b*(T_+1) + tn + 1)*128;
  float* d3 = sm->qv[nb];  const float* s3 = g_qv + tb*256;
  float* d4 = sm->pr[nb];  const float* s4 = g_pr + ((size_t)b*T_ + tn)*132;
  float* d5 = sm->pn[nb];  const float* s5 = g_pn + ((size_t)b*T_ + tn)*132;
  float* d6 = sm->bgr[nb]; const float* s6 = g_bgr + tb*12;
  for (int u = idx; u < 640; u += nthr) cp16(d0+4*u, s0+4*u);
  for (int u = idx; u < 576; u += nthr) cp16(d1+4*u, s1+4*u);
  for (int u = idx; u <  32; u += nthr) cp16(d2+4*u, s2+4*u);
  for (int u = idx; u <  64; u += nthr) cp16(d3+4*u, s3+4*u);
  for (int u = idx; u <  33; u += nthr) cp16(d4+4*u, s4+4*u);
  for (int u = idx; u <  33; u += nthr) cp16(d5+4*u, s5+4*u);
  for (int u = idx; u <   3; u += nthr) cp16(d6+4*u, s6+4*u);
}

__global__ void __launch_bounds__(NT,1) k4_kernel(
  const int* __restrict__ response,
  const float* __restrict__ W_pred, const float* __restrict__ b_pred,
  const float* __restrict__ W_ih, const float* __restrict__ W_hh,
  const float* __restrict__ b_ih, const float* __restrict__ b_hh,
  const float* __restrict__ W_batch,
  const float* __restrict__ W_bgint, const float* __restrict__ b_bgint,
  const float* __restrict__ W_hisint, const float* __restrict__ b_hisint,
  const float* __restrict__ W_inmap, const float* __restrict__ b_inmap,
  const float* __restrict__ dir_w, const float* __restrict__ heads_map,
  float* __restrict__ out)
{
  extern __shared__ unsigned char smraw[];
  SmemSeq* sm = reinterpret_cast<SmemSeq*>(smraw);
  const int b    = blockIdx.x;
  const int tid  = threadIdx.x;
  const int lane = tid & 31;
  const int wid  = tid >> 5;
  const float inv_s192 = 1.0f/sqrtf(192.0f);

  if (tid < D_){ sm->h[tid] = 0.f; sm->hbuf[tid] = 0.f; }
  if (tid == NT-1){
    float w0 = dir_w[0], w1 = dir_w[1];
    float m  = fmaxf(w0, w1);
    float e0 = expf(w0 - m), e1 = expf(w1 - m);
    sm->dw0 = e0/(e0+e1); sm->dw1 = e1/(e0+e1);
  }
  do_prefetch(sm, b, 0, 0, tid, NT);
  asm volatile("cp.async.commit_group;");
  __syncthreads();

  for (int t = 0; t < T_; ++t){
    const int cur = t & 1, nxt = cur ^ 1;
    asm volatile("cp.async.wait_group 0;");
    __syncthreads();

    const float respf = (float)response[t*B_ + b];

    // ===== P0: q h-part | his_atts | v_resp | prefetch(t+1) =====
    if (tid < 128){
      int hh = tid >> 5, dp = tid & 31;
      const ull* Wb = reinterpret_cast<const ull*>(W_batch + (size_t)hh*(3*D_*D_)) + dp;
      ull acc = 0;
      const float4* xh = reinterpret_cast<const float4*>(sm->h);
      #pragma unroll 2
      for (int k4 = 0; k4 < 16; ++k4){
        float4 x = xh[k4]; int k = k4*4;
        ull w0 = Wb[(size_t)(k+0)*32], w1 = Wb[(size_t)(k+1)*32];
        ull w2 = Wb[(size_t)(k+2)*32], w3 = Wb[(size_t)(k+3)*32];
        ffma2(acc, pack2(x.x,x.x), w0); ffma2(acc, pack2(x.y,x.y), w1);
        ffma2(acc, pack2(x.z,x.z), w2); ffma2(acc, pack2(x.w,x.w), w3);
      }
      float lo, hi; unpack2(acc, lo, hi);
      sm->q[hh*64 + 2*dp]     = sm->qv[cur][hh*64 + 2*dp]     + lo;
      sm->q[hh*64 + 2*dp + 1] = sm->qv[cur][hh*64 + 2*dp + 1] + hi;
    } else if (tid < 256){
      int u = tid - 128, d = u & 63;
      const float* w = (u < 64) ? sm->pr[cur] : sm->pn[cur];
      float a0 = 0.f, a1 = 0.f;
      int j = 0;
      for (; j + 1 <= t; j += 2){
        a0 += w[j]  *sm->hbuf[j*D_ + d];
        a1 += w[j+1]*sm->hbuf[(j+1)*D_ + d];
      }
      if (j <= t) a0 += w[j]*sm->hbuf[j*D_ + d];
      sm->his_atts[u] = a0 + a1;
    } else if (tid < 384){
      int u = tid - 256;
      float vv = sm->v[cur][u];
      sm->x10[384 + u] = vv*respf;
      sm->x10[512 + u] = vv*(1.f - respf);
    } else {
      if (t + 1 < T_){
        do_prefetch(sm, b, t+1, nxt, tid-384, 128);
        asm volatile("cp.async.commit_group;");
      }
    }
    __syncthreads();

    // ===== P1: logits (warps 0..7) | W_hisint GEMV (threads 256..447) =====
    if (wid < 8){
      for (int p = wid; p < 40; p += 8){
        int hh = p / 10;
        float a = sm->kk[cur][p*64 + lane]      * sm->q[hh*64 + lane]
                + sm->kk[cur][p*64 + 32 + lane] * sm->q[hh*64 + 32 + lane];
        #pragma unroll
        for (int o = 16; o; o >>= 1) a += __shfl_xor_sync(0xffffffffu, a, o);
        if (lane == 0) sm->logit[p] = a * inv_s192;
      }
    } else if (tid >= 256 && tid < 448){
      int i = tid - 256;                         // 0..191
      const ull* Wh = reinterpret_cast<const ull*>(W_hisint) + i;
      ull acc = 0;
      const float4* xh = reinterpret_cast<const float4*>(sm->his_atts);
      #pragma unroll 2
      for (int k4 = 0; k4 < 32; ++k4){
        float4 x = xh[k4]; int k = k4*4;
        ull w0 = Wh[(size_t)(k+0)*192], w1 = Wh[(size_t)(k+1)*192];
        ull w2 = Wh[(size_t)(k+2)*192], w3 = Wh[(size_t)(k+3)*192];
        ffma2(acc, pack2(x.x,x.x), w0); ffma2(acc, pack2(x.y,x.y), w1);
        ffma2(acc, pack2(x.z,x.z), w2); ffma2(acc, pack2(x.w,x.w), w3);
      }
      float lo, hi; unpack2(acc, lo, hi);
      sm->hisP[2*i] = lo; sm->hisP[2*i+1] = hi;
    }
    __syncthreads();

    // ===== P2: att softmax + ws (warp 0) =====
    if (wid == 0){
      if (lane < H_){
        float mx = -1e30f;
        #pragma unroll
        for (int s = 0; s < SEE_; ++s) mx = fmaxf(mx, sm->logit[lane*10 + s]);
        float sum = 0.f;
        #pragma unroll
        for (int s = 0; s < SEE_; ++s){
          float e = expf(sm->logit[lane*10 + s] - mx);
          sm->att[lane*10 + s] = e; sum += e;
        }
        float inv = 1.f/sum;
        #pragma unroll
        for (int s = 0; s < SEE_; ++s) sm->att[lane*10 + s] *= inv;
      }
      __syncwarp();
      if (lane < SEE_){
        float a = 0.f;
        #pragma unroll
        for (int hh = 0; hh < H_; ++hh) a += heads_map[hh]*sm->att[hh*10 + lane];
        sm->ws[lane] = a;
      }
    }
    __syncthreads();

    // ===== P3: bg_atts (384 thr) =====
    if (tid < 384){
      bool lo_ = tid < 192;
      int kidx = lo_ ? tid : tid - 192;
      float acc = 0.f;
      #pragma unroll
      for (int s = 0; s < SEE_; ++s){
        float r = sm->bgr[cur][s];
        acc += sm->ws[s] * sm->hvT[cur][kidx*12 + s] * (lo_ ? r : (1.f - r));
      }
      sm->bg_atts[tid] = acc;
    }
    __syncthreads();

    // ===== P4: W_bgint GEMV -> combine with hisP into x10 peer =====
    if (tid < 384){
      int seg = (tid >= 192);
      int jp  = tid - seg*192;
      const ull* Wb = reinterpret_cast<const ull*>(W_bgint) + jp;
      const float4* xb = reinterpret_cast<const float4*>(sm->bg_atts) + seg*48;
      const int kb0 = seg*192;
      ull accA = 0;
      #pragma unroll 2
      for (int k4 = 0; k4 < 48; ++k4){
        float4 x = xb[k4]; int k = kb0 + k4*4;
        ull w0 = Wb[(size_t)(k+0)*192], w1 = Wb[(size_t)(k+1)*192];
        ull w2 = Wb[(size_t)(k+2)*192], w3 = Wb[(size_t)(k+3)*192];
        ffma2(accA, pack2(x.x,x.x), w0); ffma2(accA, pack2(x.y,x.y), w1);
        ffma2(accA, pack2(x.z,x.z), w2); ffma2(accA, pack2(x.w,x.w), w3);
      }
      sm->part[seg*192 + jp] = accA;
    }
    __syncthreads();
    if (tid < 192){
      float l0,h0,l1,h1;
      unpack2(sm->part[tid],       l0, h0);
      unpack2(sm->part[192 + tid], l1, h1);
      int j = 2*tid;
      sm->x10[j]   = sm->dw0*(l0+l1 + b_bgint[j])   + sm->dw1*(sm->hisP[j]   + b_hisint[j]);
      sm->x10[j+1] = sm->dw0*(h0+h1 + b_bgint[j+1]) + sm->dw1*(sm->hisP[j+1] + b_hisint[j+1]);
    }
    __syncthreads();

    // ===== P5: gru_in (all 512, 4 ksegs) =====
    {
      int seg = tid >> 7, jp = tid & 127;
      const ull* W = reinterpret_cast<const ull*>(W_inmap) + jp;
      const float4* xv = reinterpret_cast<const float4*>(sm->x10) + seg*40;
      const int k0 = seg*160;
      ull acc = 0;
      #pragma unroll 2
      for (int k4 = 0; k4 < 40; ++k4){
        float4 x = xv[k4]; int k = k0 + k4*4;
        ull w0 = W[(size_t)(k+0)*128], w1 = W[(size_t)(k+1)*128];
        ull w2 = W[(size_t)(k+2)*128], w3 = W[(size_t)(k+3)*128];
        ffma2(acc, pack2(x.x,x.x), w0); ffma2(acc, pack2(x.y,x.y), w1);
        ffma2(acc, pack2(x.z,x.z), w2); ffma2(acc, pack2(x.w,x.w), w3);
      }
      sm->part[seg*128 + jp] = acc;
    }
    __syncthreads();
    if (tid < 128){
      float l0,h0,l1,h1,l2,h2,l3,h3;
      unpack2(sm->part[tid],        l0,h0);
      unpack2(sm->part[128 + tid],  l1,h1);
      unpack2(sm->part[256 + tid],  l2,h2);
      unpack2(sm->part[384 + tid],  l3,h3);
      int j = 2*tid;
      sm->gru_in[j]   = b_inmap[j]   + l0+l1+l2+l3;
      sm->gru_in[j+1] = b_inmap[j+1] + h0+h1+h2+h3;
    }
    __syncthreads();

    // ===== P6: gx (0..383) | gh (384..479) | pred (480..511) =====
    if (tid < 384){
      int seg = tid/96, jp = tid - seg*96;
      const ull* W = reinterpret_cast<const ull*>(W_ih) + jp;
      const float4* xv = reinterpret_cast<const float4*>(sm->gru_in) + seg*16;
      const int k0 = seg*64;
      ull acc = 0;
      #pragma unroll 2
      for (int k4 = 0; k4 < 16; ++k4){
        float4 x = xv[k4]; int k = k0 + k4*4;
        ull w0 = W[(size_t)(k+0)*96], w1 = W[(size_t)(k+1)*96];
        ull w2 = W[(size_t)(k+2)*96], w3 = W[(size_t)(k+3)*96];
        ffma2(acc, pack2(x.x,x.x), w0); ffma2(acc, pack2(x.y,x.y), w1);
        ffma2(acc, pack2(x.z,x.z), w2); ffma2(acc, pack2(x.w,x.w), w3);
      }
      sm->part[seg*96 + jp] = acc;
    } else if (tid < 480){
      int jp = tid - 384;
      const ull* W = reinterpret_cast<const ull*>(W_hh) + jp;
      const float4* xv = reinterpret_cast<const float4*>(sm->h);
      ull acc = 0;
      #pragma unroll 2
      for (int k4 = 0; k4 < 16; ++k4){
        float4 x = xv[k4]; int k = k4*4;
        ull w0 = W[(size_t)(k+0)*96], w1 = W[(size_t)(k+1)*96];
        ull w2 = W[(size_t)(k+2)*96], w3 = W[(size_t)(k+3)*96];
        ffma2(acc, pack2(x.x,x.x), w0); ffma2(acc, pack2(x.y,x.y), w1);
        ffma2(acc, pack2(x.z,x.z), w2); ffma2(acc, pack2(x.w,x.w), w3);
      }
      float lo, hi; unpack2(acc, lo, hi);
      sm->gh[2*jp]   = b_hh[2*jp]   + lo;
      sm->gh[2*jp+1] = b_hh[2*jp+1] + hi;
    } else {
      int l = tid - 480;
      float part = 0.f;
      #pragma unroll
      for (int i0 = 0; i0 < 9*D_; i0 += 32){
        int i = i0 + l;
        float xv = (i < 6*D_) ? sm->x10[i]
                 : ((i < 8*D_) ? sm->v[cur][i - 6*D_] : sm->h[i - 8*D_]);
        part += xv * W_pred[i];
      }
      #pragma unroll
      for (int o = 16; o; o >>= 1) part += __shfl_xor_sync(0xffffffffu, part, o);
      if (l == 0) out[b*T_ + t] = part + b_pred[0];
    }
    __syncthreads();
    if (tid < 96){
      float l0,h0,l1,h1,l2,h2,l3,h3;
      unpack2(sm->part[tid],       l0,h0);
      unpack2(sm->part[96 + tid],  l1,h1);
      unpack2(sm->part[192 + tid], l2,h2);
      unpack2(sm->part[288 + tid], l3,h3);
      int j = 2*tid;
      sm->gx[j]   = b_ih[j]   + l0+l1+l2+l3;
      sm->gx[j+1] = b_ih[j+1] + h0+h1+h2+h3;
    }
    __syncthreads();

    // ===== P7: GRU update =====
    if (tid < D_){
      float r  = sigmoidf_(sm->gx[tid]        + sm->gh[tid]);
      float z  = sigmoidf_(sm->gx[D_   + tid] + sm->gh[D_   + tid]);
      float n  = tanhf   (sm->gx[2*D_ + tid]  + r*sm->gh[2*D_ + tid]);
      float nh = (1.f - z)*n + z*sm->h[tid];
      sm->h[tid] = nh;
      sm->hbuf[(size_t)(t+1)*D_ + tid] = nh;
    }
    __syncthreads();
  }
}

extern "C" void kernel_launch(void* const* d_in, const int* in_sizes, int n_in,
                              void* d_out, int out_size)
{
  (void)in_sizes; (void)n_in; (void)out_size;

  const int*   prob_id      = (const int*)  d_in[0];
  const int*   skills       = (const int*)  d_in[1];
  const int*   response     = (const int*)  d_in[2];
  const int*   bg_index     = (const int*)  d_in[3];
  const int*   mem_prob_ids = (const int*)  d_in[4];
  const int*   mem_resp     = (const int*)  d_in[5];
  const int*   mem_concepts = (const int*)  d_in[6];
  const float* states_mem   = (const float*)d_in[7];
  const float* concept_emb  = (const float*)d_in[8];
  const float* prob_emb     = (const float*)d_in[9];
  const float* W_pred       = (const float*)d_in[10];
  const float* b_pred       = (const float*)d_in[11];
  const float* W_ih         = (const float*)d_in[12];
  const float* W_hh         = (const float*)d_in[13];
  const float* b_ih         = (const float*)d_in[14];
  const float* b_hh         = (const float*)d_in[15];
  const float* W_batch      = (const float*)d_in[16];
  const float* b_batch      = (const float*)d_in[17];
  const float* W_bg         = (const float*)d_in[18];
  const float* b_bg         = (const float*)d_in[19];
  const float* W_bgint      = (const float*)d_in[20];
  const float* b_bgint      = (const float*)d_in[21];
  const float* W_hisint     = (const float*)d_in[22];
  const float* b_hisint     = (const float*)d_in[23];
  const float* W_inmap      = (const float*)d_in[24];
  const float* b_inmap      = (const float*)d_in[25];
  const float* dir_w        = (const float*)d_in[26];
  const float* heads_map    = (const float*)d_in[27];

  k1_kernel<<<T_*B_, 256>>>(bg_index, mem_prob_ids, mem_resp, mem_concepts,
                            states_mem, concept_emb, prob_emb, W_bg, b_bg);
  k2_kernel<<<T_*B_, 128>>>(prob_id, skills, concept_emb, prob_emb, W_batch, b_batch);

  int k3smem = ((T_+1)*129 + 132) * (int)sizeof(float);
  cudaFuncSetAttribute(k3_kernel, cudaFuncAttributeMaxDynamicSharedMemorySize, k3smem);
  k3_kernel<<<B_, 512, k3smem>>>(response);

  cudaFuncSetAttribute(k4_kernel, cudaFuncAttributeMaxDynamicSharedMemorySize,
                       (int)sizeof(SmemSeq));
  k4_kernel<<<B_, NT, sizeof(SmemSeq)>>>(
    response, W_pred, b_pred, W_ih, W_hh, b_ih, b_hh, W_batch,
    W_bgint, b_bgint, W_hisint, b_hisint, W_inmap, b_inmap,
    dir_w, heads_map, (float*)d_out);
}